// round 17
// baseline (speedup 1.0000x reference)
#include <cuda_runtime.h>
#include <cstdint>

// HebbianNet closed form per layer:
//   z[b,o] = sum_i v[b,i]*W[o,i];  vj = relu(z + bias[o])
//   out    = vj + r*( A*S2[b] + Bc*z + (C*vj + D)*S1[b] )
// A,Bc,C,D folded from cw1/cb1/cw2/cb2; r = RATE/batch_num.
// Shapes: B=8, K=1024 all layers, O = 1024,1024,512.
//
// R16 config (best verified, 16.864us) + GEMV load amortization in the
// ROWS=8 layers: each lane computes one row x TWO batches over a
// half-size K-chunk (CHUNK 64->32, NQ 4->8), so W chunk loads are
// shared across 2 outputs: per-thread LDS drops 128->96 at equal FFMA2
// count. Layer 3 (ROWS=4) path unchanged. PDL + split-wait staging kept.

#define B_DIM   8
#define K_DIM   1024
#define RATE_F  0.001f
#define NTHR    256
#define VSTRIDE 257          // float4 row stride (conflict-free padding)

__device__ __align__(16) float g_act1[B_DIM * K_DIM];
__device__ __align__(16) float g_act2[B_DIM * K_DIM];

__device__ __forceinline__ void cp_async16(const float4* smem_dst, const float4* gsrc)
{
    uint32_t sa = (uint32_t)__cvta_generic_to_shared(smem_dst);
    asm volatile("cp.async.cg.shared.global [%0], [%1], 16;" :: "r"(sa), "l"(gsrc));
}
__device__ __forceinline__ void cp_commit() { asm volatile("cp.async.commit_group;"); }
template<int N> __device__ __forceinline__ void cp_wait()
{ asm volatile("cp.async.wait_group %0;" :: "n"(N)); }

__device__ __forceinline__ void fma2(unsigned long long& acc,
                                     unsigned long long a, unsigned long long b)
{
    asm("fma.rn.f32x2 %0, %1, %2, %3;" : "=l"(acc) : "l"(a), "l"(b), "l"(acc));
}

template<int ROWS, bool PDL_WAIT>   // ROWS: 8 (layers 1-2), 4 (layer 3)
__global__ __launch_bounds__(NTHR, 1)
void hebbian_layer(const float* __restrict__ V,      // (8,1024)
                   const float* __restrict__ W,      // (O,1024)
                   const float* __restrict__ bias,   // (O,)
                   const float* __restrict__ cw1, const float* __restrict__ cb1,
                   const float* __restrict__ cw2, const float* __restrict__ cb2,
                   const int*   __restrict__ bn,
                   float*       __restrict__ out,    // (8,O)
                   int O)
{
    constexpr int SLOTS = ROWS * 8;            // (row,batch) identities: 64 / 32
    constexpr int NQ    = 8;                   // K-chunks (both paths now 8)
    constexpr int CHUNK = 32;                  // float4 per chunk (8*32*4 = K)
    constexpr int REDN  = NQ * SLOTS;          // 512 (ROWS=8) / 256 (ROWS=4)

    extern __shared__ float4 sm[];
    float4* Vs  = sm;                          // 8 * 257 float4
    float4* Ws  = Vs + 8 * VSTRIDE;            // ROWS * 257 float4
    float*  red = (float*)(Ws + ROWS * VSTRIDE);   // REDN floats
    float*  S1s = red + REDN;
    float*  S2s = S1s + 8;

    const int tid  = threadIdx.x;
    const int wid  = tid >> 5;
    const int lane = tid & 31;
    const int o_base = blockIdx.x * ROWS;

    // let dependent kernels launch immediately (their W staging overlaps us)
    asm volatile("griddepcontrol.launch_dependents;");

    const float4* Wg = (const float4*)(W + (size_t)o_base * K_DIM);
    const float4* Vg = (const float4*)V;

    if (!PDL_WAIT) {
        // layer 1: V first (stats can start at wait<1>), then W
#pragma unroll
        for (int m = 0; m < 8; ++m) {
            int x = tid + m * NTHR;
            cp_async16(&Vs[(x >> 8) * VSTRIDE + (x & 255)], &Vg[x]);
        }
        cp_commit();                          // group: V
#pragma unroll
        for (int m = 0; m < ROWS; ++m) {
            int x = tid + m * NTHR;
            cp_async16(&Ws[(x >> 8) * VSTRIDE + (x & 255)], &Wg[x]);
        }
        cp_commit();                          // group: W
    } else {
        // PDL layers: W goes pre-wait (independent of predecessor)
#pragma unroll
        for (int m = 0; m < ROWS; ++m) {
            int x = tid + m * NTHR;
            cp_async16(&Ws[(x >> 8) * VSTRIDE + (x & 255)], &Wg[x]);
        }
        cp_commit();                          // group: W (lands during predecessor)
    }

    // ---- uniform scalar folding + bias prefetch (overlap load latency) -----
    float A = 0.f, Bc = 0.f, C = 0.f, D = 0.f;
#pragma unroll
    for (int h = 0; h < 8; ++h) {
        float e = cw2[h];
        A  = fmaf(e, cw1[3*h + 0], A);
        Bc = fmaf(e, cw1[3*h + 1], Bc);
        C  = fmaf(e, cw1[3*h + 2], C);
        D  = fmaf(e, cb1[h],       D);
    }
    D += cb2[0];
    const float rr = RATE_F / (float)bn[0];

    float bias_r = 0.f;
    if (tid < SLOTS) bias_r = bias[o_base + (tid >> 3)];

    if (PDL_WAIT) {
        // wait for predecessor grid completion, then stage V
        asm volatile("griddepcontrol.wait;" ::: "memory");
#pragma unroll
        for (int m = 0; m < 8; ++m) {
            int x = tid + m * NTHR;
            cp_async16(&Vs[(x >> 8) * VSTRIDE + (x & 255)], &Vg[x]);
        }
        cp_commit();                          // group: V
    }

    // !PDL: groups [V, W] -> wait<1> = V done (stats OK, W may fly)
    // PDL : groups [W, V] -> V is newest, must wait<0> before stats
    if (!PDL_WAIT) cp_wait<1>();
    else           cp_wait<0>();
    __syncthreads();

    // ---- per-batch stats: warp w (0..7) -> batch w --------------------------
    {
        float s1 = 0.f, s2 = 0.f;
#pragma unroll
        for (int m = 0; m < 8; ++m) {
            float4 v = Vs[wid * VSTRIDE + m * 32 + lane];
            s1 += v.x + v.y + v.z + v.w;
            s2 = fmaf(v.x, v.x, s2); s2 = fmaf(v.y, v.y, s2);
            s2 = fmaf(v.z, v.z, s2); s2 = fmaf(v.w, v.w, s2);
        }
#pragma unroll
        for (int off = 16; off > 0; off >>= 1) {
            s1 += __shfl_xor_sync(0xffffffffu, s1, off);
            s2 += __shfl_xor_sync(0xffffffffu, s2, off);
        }
        if (lane == 0) { S1s[wid] = s1; S2s[wid] = s2; }
    }

    if (!PDL_WAIT) {            // W must be resident before the GEMV reads it
        cp_wait<0>();
        __syncthreads();
    }

    // ---- GEMV: warp = K-eighth (q=wid, CHUNK=32 f4) -------------------------
    const int q = wid;          // 0..7

    if (ROWS == 8) {
        // lane = (row, batch-pair): 1 row x 2 batches, W loads amortized 2x
        const int row = lane >> 2;        // 0..7
        const int bp  = lane & 3;         // batches bp and bp+4

        const ulonglong2* wp  = (const ulonglong2*)(Ws + row      * VSTRIDE + q * CHUNK);
        const ulonglong2* vp0 = (const ulonglong2*)(Vs + bp       * VSTRIDE + q * CHUNK);
        const ulonglong2* vp1 = (const ulonglong2*)(Vs + (bp + 4) * VSTRIDE + q * CHUNK);

        unsigned long long A0 = 0ull, A1 = 0ull, A2 = 0ull, A3 = 0ull;
#pragma unroll
        for (int i = 0; i < CHUNK; i += 2) {
            ulonglong2 w0 = wp[i],   w1 = wp[i+1];
            ulonglong2 u0 = vp0[i],  u1 = vp0[i+1];
            ulonglong2 t0 = vp1[i],  t1 = vp1[i+1];
            fma2(A0, w0.x, u0.x);  fma2(A1, w0.y, u0.y);
            fma2(A0, w1.x, u1.x);  fma2(A1, w1.y, u1.y);
            fma2(A2, w0.x, t0.x);  fma2(A3, w0.y, t0.y);
            fma2(A2, w1.x, t1.x);  fma2(A3, w1.y, t1.y);
        }
        float2 f0 = *(float2*)&A0, f1 = *(float2*)&A1;
        float2 f2 = *(float2*)&A2, f3 = *(float2*)&A3;
        red[q * 64 + row * 8 + bp    ] = (f0.x + f0.y) + (f1.x + f1.y);
        red[q * 64 + row * 8 + bp + 4] = (f2.x + f2.y) + (f3.x + f3.y);
    } else {
        // ROWS=4 path: unchanged from the verified config
        const int s   = lane;             // 0..31
        const int row = lane >> 3;        // 0..3
        const int b   = lane & 7;

        const ulonglong2* vp = (const ulonglong2*)(Vs + b   * VSTRIDE + q * CHUNK);
        const ulonglong2* wp = (const ulonglong2*)(Ws + row * VSTRIDE + q * CHUNK);

        unsigned long long A0 = 0ull, A1 = 0ull, A2 = 0ull, A3 = 0ull;
#pragma unroll
        for (int i = 0; i < CHUNK; i += 2) {
            ulonglong2 v0 = vp[i],   w0 = wp[i];
            ulonglong2 v1 = vp[i+1], w1 = wp[i+1];
            fma2(A0, w0.x, v0.x);  fma2(A1, w0.y, v0.y);
            fma2(A2, w1.x, v1.x);  fma2(A3, w1.y, v1.y);
        }
        float2 f0 = *(float2*)&A0, f1 = *(float2*)&A1;
        float2 f2 = *(float2*)&A2, f3 = *(float2*)&A3;
        red[q * SLOTS + s] = ((f0.x + f0.y) + (f1.x + f1.y))
                           + ((f2.x + f2.y) + (f3.x + f3.y));
    }
    __syncthreads();

    // ---- combine K-chunks + epilogue ----------------------------------------
    if (tid < SLOTS) {
        const int r  = tid >> 3;
        const int bb = tid & 7;
        const int o  = o_base + r;

        float z = 0.f;
#pragma unroll
        for (int qq = 0; qq < NQ; ++qq) z += red[qq * SLOTS + tid];

        float vj = fmaxf(z + bias_r, 0.f);
        float sh = fmaf(A, S2s[bb], fmaf(Bc, z, (C * vj + D) * S1s[bb]));
        out[(size_t)bb * O + o] = fmaf(rr, sh, vj);
    }
}

extern "C" void kernel_launch(void* const* d_in, const int* in_sizes, int n_in,
                              void* d_out, int out_size)
{
    (void)in_sizes; (void)n_in; (void)out_size;
    const float* x   = (const float*)d_in[0];
    const float* W1  = (const float*)d_in[1];
    const float* b1  = (const float*)d_in[2];
    const float* W2  = (const float*)d_in[3];
    const float* b2  = (const float*)d_in[4];
    const float* W3  = (const float*)d_in[5];
    const float* b3  = (const float*)d_in[6];
    const float* cw1 = (const float*)d_in[7];
    const float* cb1 = (const float*)d_in[8];
    const float* cw2 = (const float*)d_in[9];
    const float* cb2 = (const float*)d_in[10];
    const int*   bn  = (const int*)d_in[11];
    float* outp = (float*)d_out;

    float *act1, *act2;
    cudaGetSymbolAddress((void**)&act1, g_act1);
    cudaGetSymbolAddress((void**)&act2, g_act2);

    const int smem8 = (8 + 8) * VSTRIDE * 16 + 512 * 4 + 16 * 4;
    const int smem4 = (8 + 4) * VSTRIDE * 16 + 256 * 4 + 16 * 4;
    cudaFuncSetAttribute(hebbian_layer<8, false>,
                         cudaFuncAttributeMaxDynamicSharedMemorySize, smem8);
    cudaFuncSetAttribute(hebbian_layer<8, true>,
                         cudaFuncAttributeMaxDynamicSharedMemorySize, smem8);
    cudaFuncSetAttribute(hebbian_layer<4, true>,
                         cudaFuncAttributeMaxDynamicSharedMemorySize, smem4);

    // layer 1: x -> act1 (plain launch; V-first split-wait staging)
    hebbian_layer<8, false><<<128, NTHR, smem8>>>(
        x, W1, b1, cw1, cb1, cw2, cb2, bn, act1, 1024);

    // layers 2,3: PDL launches (overlap prologue with predecessor)
    cudaLaunchAttribute at[1];
    at[0].id = cudaLaunchAttributeProgrammaticStreamSerialization;
    at[0].val.programmaticStreamSerializationAllowed = 1;

    cudaLaunchConfig_t cfg = {};
    cfg.gridDim  = dim3(128, 1, 1);
    cfg.blockDim = dim3(NTHR, 1, 1);
    cfg.stream   = 0;            // legacy stream (mapped by capture)
    cfg.attrs    = at;
    cfg.numAttrs = 1;

    cfg.dynamicSmemBytes = smem8;
    cudaLaunchKernelEx(&cfg, hebbian_layer<8, true>,
                       (const float*)act1, W2, b2, cw1, cb1, cw2, cb2, bn,
                       (float*)act2, 1024);

    cfg.dynamicSmemBytes = smem4;
    cudaLaunchKernelEx(&cfg, hebbian_layer<4, true>,
                       (const float*)act2, W3, b3, cw1, cb1, cw2, cb2, bn,
                       outp, 512);
}